// round 1
// baseline (speedup 1.0000x reference)
#include <cuda_runtime.h>

// ---------------------------------------------------------------------------
// DSSIM loss: 1 - mean(SSIM(X, Y)), 11x11 Gaussian window sigma=1.5,
// depthwise over C=3, zero ("SAME") padding, HWC fp32 inputs 2160x3840x3.
//
// Strategy: separable Gaussian. Channel-interleaved HWC layout => horizontal
// conv is stride-3 in the fused (w*C+c) index; vertical conv is row-stride.
// Each thread owns one fused column and streams rows: horizontal 11-tap conv
// from a shared-memory row strip, vertical 11-tap conv from a register ring
// (unrolled by 11 so all ring indices are compile-time => pure registers).
// Gaussian weights are fp32 literals => immediate-form FFMA (2x throughput).
// ---------------------------------------------------------------------------

static constexpr int H    = 2160;
static constexpr int IMGW = 3840;
static constexpr int CC   = 3;
static constexpr int WC   = IMGW * CC;          // 11520 fused columns
static constexpr int BX   = 256;                // threads = fused cols / block
static constexpr int HALO = 15;                 // 5 taps * stride 3
static constexpr int ROWW = BX + 2 * HALO;      // 286 loaded cols per row
static constexpr int ROWP = 288;                // padded smem row width
static constexpr int CH   = 11;                 // rows per smem chunk (= ring)
static constexpr int OH   = 78;                 // output rows per block
static constexpr int NCH  = (OH + 10) / CH;     // 8 chunks (88 input rows)
static constexpr int GX   = WC / BX;            // 45
static constexpr int GY   = (H + OH - 1) / OH;  // 28
static constexpr int NBLK = GX * GY;            // 1260
static constexpr float SSIM_C1 = 1e-4f;         // 0.01^2
static constexpr float SSIM_C2 = 9e-4f;         // 0.03^2

__device__ float g_partial[NBLK];

__global__ void __launch_bounds__(BX, 2)
ssim_main(const float* __restrict__ X, const float* __restrict__ Y) {
    __shared__ float2 buf[CH][ROWP];
    __shared__ float  red[BX];

    // Normalized Gaussian, sigma=1.5, 11 taps (symmetric).
    const float GW[11] = {
        0.00102839f, 0.00759875f, 0.03600078f, 0.10936080f, 0.21300554f,
        0.26601173f,
        0.21300554f, 0.10936080f, 0.03600078f, 0.00759875f, 0.00102839f
    };

    const int tid = threadIdx.x;
    const int cb  = blockIdx.x * BX;       // fused-column base of this block
    const int Rs  = blockIdx.y * OH;       // first output row of this block

    // Register ring: horizontal conv results for the last 11 input rows.
    float hx[11], hy[11], hxx[11], hyy[11], hxy[11];
    float acc = 0.f;

#pragma unroll 1
    for (int ch = 0; ch < NCH; ++ch) {
        const int r0 = Rs - 5 + ch * CH;   // first input row of this chunk

        // ---- cooperative load of 11 rows of {x,y} with halo, zero-padded ----
#pragma unroll
        for (int j = 0; j < CH; ++j) {
            const int row = r0 + j;
            const bool rok = (row >= 0) && (row < H);
            const float* xr = X + row * WC;
            const float* yr = Y + row * WC;
#pragma unroll
            for (int i = tid; i < ROWW; i += BX) {
                const int g = cb - HALO + i;
                float xv = 0.f, yv = 0.f;
                if (rok && g >= 0 && g < WC) { xv = xr[g]; yv = yr[g]; }
                buf[j][i] = make_float2(xv, yv);
            }
        }
        __syncthreads();

        // ---- horizontal conv + ring update + (when warm) vertical conv ----
#pragma unroll
        for (int j = 0; j < CH; ++j) {
            float sx = 0.f, sy = 0.f, sxx = 0.f, syy = 0.f, sxy = 0.f;
#pragma unroll
            for (int k = 0; k < 11; ++k) {
                const float2 v = buf[j][tid + 3 * k];
                sx  = fmaf(v.x,       GW[k], sx);
                sy  = fmaf(v.y,       GW[k], sy);
                sxx = fmaf(v.x * v.x, GW[k], sxx);
                syy = fmaf(v.y * v.y, GW[k], syy);
                sxy = fmaf(v.x * v.y, GW[k], sxy);
            }
            hx[j] = sx; hy[j] = sy; hxx[j] = sxx; hyy[j] = syy; hxy[j] = sxy;

            const int t  = ch * CH + j;        // row-stream step (phase = j)
            const int ro = Rs + t - 10;        // emitted output row
            if (t >= 10 && ro < H) {
                float mux = 0.f, muy = 0.f, Sxx = 0.f, Syy = 0.f, Sxy = 0.f;
#pragma unroll
                for (int k = 0; k < 11; ++k) {
                    const int s = (j + 1 + k) % 11;   // compile-time slot
                    mux = fmaf(hx[s],  GW[k], mux);
                    muy = fmaf(hy[s],  GW[k], muy);
                    Sxx = fmaf(hxx[s], GW[k], Sxx);
                    Syy = fmaf(hyy[s], GW[k], Syy);
                    Sxy = fmaf(hxy[s], GW[k], Sxy);
                }
                const float mux2 = mux * mux;
                const float muy2 = muy * muy;
                const float muxy = mux * muy;
                const float vx  = Sxx - mux2;
                const float vy  = Syy - muy2;
                const float vxy = Sxy - muxy;
                const float num = (2.f * muxy + SSIM_C1) * (2.f * vxy + SSIM_C2);
                const float den = (mux2 + muy2 + SSIM_C1) * (vx + vy + SSIM_C2);
                acc += __fdividef(num, den);
            }
        }
        __syncthreads();
    }

    // ---- block reduction (deterministic tree) ----
    red[tid] = acc;
    __syncthreads();
#pragma unroll
    for (int s = BX / 2; s > 0; s >>= 1) {
        if (tid < s) red[tid] += red[tid + s];
        __syncthreads();
    }
    if (tid == 0) g_partial[blockIdx.y * GX + blockIdx.x] = red[0];
}

__global__ void ssim_reduce(float* __restrict__ out) {
    __shared__ double red[256];
    double s = 0.0;
    for (int i = threadIdx.x; i < NBLK; i += 256) s += (double)g_partial[i];
    red[threadIdx.x] = s;
    __syncthreads();
    for (int k = 128; k > 0; k >>= 1) {
        if (threadIdx.x < k) red[threadIdx.x] += red[threadIdx.x + k];
        __syncthreads();
    }
    if (threadIdx.x == 0) {
        const double n = (double)H * (double)WC;   // 24,883,200
        out[0] = (float)(1.0 - red[0] / n);
    }
}

extern "C" void kernel_launch(void* const* d_in, const int* in_sizes, int n_in,
                              void* d_out, int out_size) {
    const float* X = (const float*)d_in[0];
    const float* Y = (const float*)d_in[1];
    dim3 grid(GX, GY);
    ssim_main<<<grid, BX>>>(X, Y);
    ssim_reduce<<<1, 256>>>((float*)d_out);
}

// round 2
// speedup vs baseline: 1.2328x; 1.2328x over previous
#include <cuda_runtime.h>

// ---------------------------------------------------------------------------
// DSSIM loss: 1 - mean(SSIM(X,Y)), 11x11 Gaussian (sigma=1.5), depthwise C=3,
// zero SAME padding, HWC fp32 2160x3840x3.
//
// Separable blur, row-streaming, register ring for the vertical pass.
// Round-2: packed f32x2 math for the (x,y) and (xx,yy) field pairs,
// vectorized guard-free smem fill for interior blocks, OH=122.
// ---------------------------------------------------------------------------

using u64 = unsigned long long;

static constexpr int H    = 2160;
static constexpr int WC   = 3840 * 3;            // 11520 fused cols (w*C+c)
static constexpr int BX   = 256;
static constexpr int LW   = 288;                 // loaded cols: global [cb-16, cb+272)
static constexpr int CH   = 11;                  // rows per chunk (= ring depth)
static constexpr int OH   = 122;                 // output rows per block
static constexpr int NCH  = (OH + 10) / CH;      // 12 chunks = 132 input rows
static constexpr int GX   = WC / BX;             // 45
static constexpr int GY   = (H + OH - 1) / OH;   // 18
static constexpr int NBLK = GX * GY;             // 810
static constexpr float SSIM_C1 = 1e-4f;
static constexpr float SSIM_C2 = 9e-4f;

__device__ float g_partial[NBLK];

__device__ __forceinline__ u64 pk2(float lo, float hi) {
    u64 r; asm("mov.b64 %0, {%1, %2};" : "=l"(r) : "f"(lo), "f"(hi)); return r;
}
__device__ __forceinline__ float2 up2(u64 a) {
    float2 f; asm("mov.b64 {%0, %1}, %2;" : "=f"(f.x), "=f"(f.y) : "l"(a)); return f;
}
__device__ __forceinline__ u64 fma2(u64 a, u64 b, u64 c) {
    u64 d; asm("fma.rn.f32x2 %0, %1, %2, %3;" : "=l"(d) : "l"(a), "l"(b), "l"(c)); return d;
}
__device__ __forceinline__ u64 mul2(u64 a, u64 b) {
    u64 d; asm("mul.rn.f32x2 %0, %1, %2;" : "=l"(d) : "l"(a), "l"(b)); return d;
}

__global__ void __launch_bounds__(BX, 2)
ssim_main(const float* __restrict__ X, const float* __restrict__ Y) {
    __shared__ float2 buf[CH][LW];     // interleaved {x,y}, 25.3 KB
    __shared__ float  red[BX];

    const float GWs[11] = {
        0.00102839f, 0.00759875f, 0.03600078f, 0.10936080f, 0.21300554f,
        0.26601173f,
        0.21300554f, 0.10936080f, 0.03600078f, 0.00759875f, 0.00102839f
    };
    u64 GW2[11];
#pragma unroll
    for (int k = 0; k < 11; ++k) GW2[k] = pk2(GWs[k], GWs[k]);

    const int tid = threadIdx.x;
    const int cb  = blockIdx.x * BX;
    const int Rs  = blockIdx.y * OH;
    const bool xin = (blockIdx.x > 0) && (blockIdx.x < GX - 1);

    // Rings: packed (hx,hy), packed (hxx,hyy), scalar hxy.
    u64 rxy[11], rss[11]; float rxy1[11];
    float acc = 0.f;

#pragma unroll 1
    for (int ch = 0; ch < NCH; ++ch) {
        const int r0 = Rs - 5 + ch * CH;      // first input row of chunk

        // ---- fill 11 rows of interleaved {x,y}, 2 cols per active thread ----
        if (tid < LW / 2) {
            const int c0 = 2 * tid;           // local column pair
            const int g0 = cb - 16 + c0;      // global fused column
#pragma unroll
            for (int j = 0; j < CH; ++j) {
                const int row = r0 + j;
                float x0 = 0.f, x1 = 0.f, y0 = 0.f, y1 = 0.f;
                if (row >= 0 && row < H) {
                    const size_t b = (size_t)row * WC;
                    if (xin) {
                        const float2 xv = *(const float2*)(X + b + g0);
                        const float2 yv = *(const float2*)(Y + b + g0);
                        x0 = xv.x; x1 = xv.y; y0 = yv.x; y1 = yv.y;
                    } else {
                        if (g0 >= 0 && g0 < WC)         { x0 = X[b + g0];     y0 = Y[b + g0];     }
                        if (g0 + 1 >= 0 && g0 + 1 < WC) { x1 = X[b + g0 + 1]; y1 = Y[b + g0 + 1]; }
                    }
                }
                *(float4*)(&buf[j][c0]) = make_float4(x0, y0, x1, y1);
            }
        }
        __syncthreads();

        // ---- horizontal conv + ring update + vertical conv when warm ----
#pragma unroll
        for (int j = 0; j < CH; ++j) {
            u64 sxy = 0ull, sss = 0ull; float sxy1 = 0.f;
#pragma unroll
            for (int k = 0; k < 11; ++k) {
                const float2 vf = buf[j][tid + 1 + 3 * k];   // LDS.64 pair
                const u64 v = pk2(vf.x, vf.y);
                sxy  = fma2(v, GW2[k], sxy);                 // (Sx, Sy)
                sss  = fma2(mul2(v, v), GW2[k], sss);        // (Sxx, Syy)
                sxy1 = fmaf(vf.x * vf.y, GWs[k], sxy1);      // Sxy (scalar)
            }
            rxy[j] = sxy; rss[j] = sss; rxy1[j] = sxy1;

            const int t  = ch * CH + j;
            const int ro = Rs + t - 10;
            if (t >= 10 && ro < H) {
                u64 mu = 0ull, S = 0ull; float Sxy = 0.f;
#pragma unroll
                for (int k = 0; k < 11; ++k) {
                    const int s = (j + 1 + k) % 11;          // compile-time slot
                    mu  = fma2(rxy[s], GW2[k], mu);
                    S   = fma2(rss[s], GW2[k], S);
                    Sxy = fmaf(rxy1[s], GWs[k], Sxy);
                }
                const float2 m  = up2(mu);
                const float2 Sv = up2(S);
                const float mux2 = m.x * m.x;
                const float muy2 = m.y * m.y;
                const float muxy = m.x * m.y;
                const float num = (2.f * muxy + SSIM_C1) * (2.f * (Sxy - muxy) + SSIM_C2);
                const float den = (mux2 + muy2 + SSIM_C1) *
                                  ((Sv.x - mux2) + (Sv.y - muy2) + SSIM_C2);
                acc += __fdividef(num, den);
            }
        }
        __syncthreads();
    }

    // ---- deterministic block reduction ----
    red[tid] = acc;
    __syncthreads();
#pragma unroll
    for (int s = BX / 2; s > 0; s >>= 1) {
        if (tid < s) red[tid] += red[tid + s];
        __syncthreads();
    }
    if (tid == 0) g_partial[blockIdx.y * GX + blockIdx.x] = red[0];
}

__global__ void ssim_reduce(float* __restrict__ out) {
    __shared__ double red[256];
    double s = 0.0;
    for (int i = threadIdx.x; i < NBLK; i += 256) s += (double)g_partial[i];
    red[threadIdx.x] = s;
    __syncthreads();
    for (int k = 128; k > 0; k >>= 1) {
        if (threadIdx.x < k) red[threadIdx.x] += red[threadIdx.x + k];
        __syncthreads();
    }
    if (threadIdx.x == 0) {
        const double n = (double)H * (double)WC;
        out[0] = (float)(1.0 - red[0] / n);
    }
}

extern "C" void kernel_launch(void* const* d_in, const int* in_sizes, int n_in,
                              void* d_out, int out_size) {
    const float* X = (const float*)d_in[0];
    const float* Y = (const float*)d_in[1];
    dim3 grid(GX, GY);
    ssim_main<<<grid, BX>>>(X, Y);
    ssim_reduce<<<1, 256>>>((float*)d_out);
}

// round 3
// speedup vs baseline: 1.8015x; 1.4614x over previous
#include <cuda_runtime.h>

// ---------------------------------------------------------------------------
// DSSIM loss: 1 - mean(SSIM(X,Y)), 11x11 Gaussian (sigma=1.5), depthwise C=3,
// zero SAME padding, HWC fp32 2160x3840x3.
//
// Separable blur, row-streaming, packed-f32x2 register ring for the vertical
// pass. Round-3: software-pipelined double-buffered loads (prefetch next
// chunk's rows one per compute step, one barrier per chunk) + exact-2-wave
// grid (585 blocks @ 2 CTA/SM on 148 SMs).
// ---------------------------------------------------------------------------

using u64 = unsigned long long;

static constexpr int H    = 2160;
static constexpr int WC   = 3840 * 3;            // 11520 fused cols (w*C+c)
static constexpr int BX   = 256;
static constexpr int LW   = 288;                 // loaded cols [cb-16, cb+272)
static constexpr int CH   = 11;                  // rows per chunk (= ring depth)
static constexpr int OH   = 177;                 // output rows per block
static constexpr int NCH  = (OH + 10) / CH;      // 17 chunks, 187 rows exactly
static constexpr int GX   = WC / BX;             // 45
static constexpr int GY   = 13;                  // 13*177 = 2301 >= 2160
static constexpr int NBLK = GX * GY;             // 585 = 1.98 waves @ 296
static constexpr int SMEM_BYTES = 2 * CH * LW * (int)sizeof(float2); // 50688
static constexpr float SSIM_C1 = 1e-4f;
static constexpr float SSIM_C2 = 9e-4f;

__device__ float g_partial[NBLK];

__device__ __forceinline__ u64 pk2(float lo, float hi) {
    u64 r; asm("mov.b64 %0, {%1, %2};" : "=l"(r) : "f"(lo), "f"(hi)); return r;
}
__device__ __forceinline__ float2 up2(u64 a) {
    float2 f; asm("mov.b64 {%0, %1}, %2;" : "=f"(f.x), "=f"(f.y) : "l"(a)); return f;
}
__device__ __forceinline__ u64 fma2(u64 a, u64 b, u64 c) {
    u64 d; asm("fma.rn.f32x2 %0, %1, %2, %3;" : "=l"(d) : "l"(a), "l"(b), "l"(c)); return d;
}
__device__ __forceinline__ u64 mul2(u64 a, u64 b) {
    u64 d; asm("mul.rn.f32x2 %0, %1, %2;" : "=l"(d) : "l"(a), "l"(b)); return d;
}

extern __shared__ float2 dbuf[];   // [2][CH][LW]
#define BUF(p, j, i) dbuf[((p) * CH + (j)) * LW + (i)]

__global__ void __launch_bounds__(BX, 2)
ssim_main(const float* __restrict__ X, const float* __restrict__ Y) {
    __shared__ float red[BX];

    const float GWs[11] = {
        0.00102839f, 0.00759875f, 0.03600078f, 0.10936080f, 0.21300554f,
        0.26601173f,
        0.21300554f, 0.10936080f, 0.03600078f, 0.00759875f, 0.00102839f
    };
    u64 GW2[11];
#pragma unroll
    for (int k = 0; k < 11; ++k) GW2[k] = pk2(GWs[k], GWs[k]);

    const int  tid = threadIdx.x;
    const int  cb  = blockIdx.x * BX;
    const int  Rs  = blockIdx.y * OH;
    const bool xin = (blockIdx.x > 0) && (blockIdx.x < GX - 1);
    const bool ldr = tid < LW / 2;        // 144 loader threads, 2 col-pairs each
    const int  c0  = 2 * tid;             // local column pair base
    const int  g0  = cb - 16 + c0;        // global fused column

    // Load one image row (both images) for this thread's 2 columns.
    auto ldrow = [&](int row, float& x0, float& y0, float& x1, float& y1) {
        x0 = x1 = y0 = y1 = 0.f;
        if (row >= 0 && row < H) {
            const size_t b = (size_t)row * WC;
            if (xin) {
                const float2 xv = *(const float2*)(X + b + g0);
                const float2 yv = *(const float2*)(Y + b + g0);
                x0 = xv.x; x1 = xv.y; y0 = yv.x; y1 = yv.y;
            } else {
                if (g0 >= 0 && g0 < WC)         { x0 = X[b + g0];     y0 = Y[b + g0];     }
                if (g0 + 1 >= 0 && g0 + 1 < WC) { x1 = X[b + g0 + 1]; y1 = Y[b + g0 + 1]; }
            }
        }
    };

    // ---- prologue: fill buffer 0 with chunk 0 ----
    if (ldr) {
#pragma unroll
        for (int j = 0; j < CH; ++j) {
            float x0, y0, x1, y1;
            ldrow(Rs - 5 + j, x0, y0, x1, y1);
            *(float4*)(&BUF(0, j, c0)) = make_float4(x0, y0, x1, y1);
        }
    }
    __syncthreads();

    // Rings: packed (hx,hy), packed (hxx,hyy), scalar hxy.
    u64 rxy[11], rss[11]; float rxy1[11];
    float acc = 0.f;

#pragma unroll 1
    for (int ch = 0; ch < NCH; ++ch) {
        const int  pc  = ch & 1;             // compute buffer
        const int  pn  = pc ^ 1;             // prefetch buffer
        const int  rn0 = Rs - 5 + (ch + 1) * CH;
        const bool pf  = (ch + 1 < NCH) && ldr;
        float px0, py0, px1, py1;

#pragma unroll
        for (int j = 0; j < CH; ++j) {
            // -- pipelined prefetch of next chunk: STS(row j-1), LDG(row j) --
            if (pf) {
                if (j > 0)
                    *(float4*)(&BUF(pn, j - 1, c0)) = make_float4(px0, py0, px1, py1);
                ldrow(rn0 + j, px0, py0, px1, py1);
            }

            // -- horizontal 11-tap conv for row j of current chunk --
            u64 sxy = 0ull, sss = 0ull; float sxy1 = 0.f;
#pragma unroll
            for (int k = 0; k < 11; ++k) {
                const float2 vf = BUF(pc, j, tid + 1 + 3 * k);   // LDS.64
                const u64 v = pk2(vf.x, vf.y);
                sxy  = fma2(v, GW2[k], sxy);                     // (Sx, Sy)
                sss  = fma2(mul2(v, v), GW2[k], sss);            // (Sxx, Syy)
                sxy1 = fmaf(vf.x * vf.y, GWs[k], sxy1);          // Sxy
            }
            rxy[j] = sxy; rss[j] = sss; rxy1[j] = sxy1;

            // -- vertical conv + SSIM once the ring is warm --
            const int t  = ch * CH + j;
            const int ro = Rs + t - 10;
            if (t >= 10 && ro < H) {
                u64 mu = 0ull, S = 0ull; float Sxy = 0.f;
#pragma unroll
                for (int k = 0; k < 11; ++k) {
                    const int s = (j + 1 + k) % 11;              // compile-time
                    mu  = fma2(rxy[s], GW2[k], mu);
                    S   = fma2(rss[s], GW2[k], S);
                    Sxy = fmaf(rxy1[s], GWs[k], Sxy);
                }
                const float2 m  = up2(mu);
                const float2 Sv = up2(S);
                const float mux2 = m.x * m.x;
                const float muy2 = m.y * m.y;
                const float muxy = m.x * m.y;
                const float num = (2.f * muxy + SSIM_C1) * (2.f * (Sxy - muxy) + SSIM_C2);
                const float den = (mux2 + muy2 + SSIM_C1) *
                                  ((Sv.x - mux2) + (Sv.y - muy2) + SSIM_C2);
                acc += __fdividef(num, den);
            }
        }

        if (pf)   // last prefetched row of next chunk
            *(float4*)(&BUF(pn, CH - 1, c0)) = make_float4(px0, py0, px1, py1);
        __syncthreads();
    }

    // ---- deterministic block reduction ----
    red[tid] = acc;
    __syncthreads();
#pragma unroll
    for (int s = BX / 2; s > 0; s >>= 1) {
        if (tid < s) red[tid] += red[tid + s];
        __syncthreads();
    }
    if (tid == 0) g_partial[blockIdx.y * GX + blockIdx.x] = red[0];
}

__global__ void ssim_reduce(float* __restrict__ out) {
    __shared__ double red[256];
    double s = 0.0;
    for (int i = threadIdx.x; i < NBLK; i += 256) s += (double)g_partial[i];
    red[threadIdx.x] = s;
    __syncthreads();
    for (int k = 128; k > 0; k >>= 1) {
        if (threadIdx.x < k) red[threadIdx.x] += red[threadIdx.x + k];
        __syncthreads();
    }
    if (threadIdx.x == 0) {
        const double n = (double)H * (double)WC;
        out[0] = (float)(1.0 - red[0] / n);
    }
}

extern "C" void kernel_launch(void* const* d_in, const int* in_sizes, int n_in,
                              void* d_out, int out_size) {
    const float* X = (const float*)d_in[0];
    const float* Y = (const float*)d_in[1];
    cudaFuncSetAttribute(ssim_main, cudaFuncAttributeMaxDynamicSharedMemorySize,
                         SMEM_BYTES);
    dim3 grid(GX, GY);
    ssim_main<<<grid, BX, SMEM_BYTES>>>(X, Y);
    ssim_reduce<<<1, 256>>>((float*)d_out);
}